// round 1
// baseline (speedup 1.0000x reference)
#include <cuda_runtime.h>
#include <math.h>

#define NB   512
#define NT   60
#define NE   300
#define NH   512
#define NM   256
#define NB2  1024          // both sequences batched
#define NG   2048          // 4*H
#define NHC  2053          // 4*(H+1)+1

__device__ float g_xW[(size_t)NT * NB2 * NG];  // [t][b2][4H] precomputed x@Wx
__device__ float g_z [NB2 * NG];
__device__ float g_h [NB2 * NH];
__device__ float g_c [NB2 * NH];
__device__ float g_hc[NB * NHC];
__device__ float g_e1[NB * NM];

__device__ __forceinline__ float sigmf(float x) { return 1.0f / (1.0f + expf(-x)); }

// ---------------------------------------------------------------------------
// Zero the LSTM state (must re-zero every call: deterministic launches)
// ---------------------------------------------------------------------------
__global__ void zero_state() {
    int i = blockIdx.x * blockDim.x + threadIdx.x;
    if (i < NB2 * NH) { g_h[i] = 0.0f; g_c[i] = 0.0f; }
}

// ---------------------------------------------------------------------------
// GEMM 1: gather-fused input projection.
// C[61440, 2048] = emb[tok(r), :300] @ Wx[300, 2048], row r = t*1024 + b2
// 128x128 tile, BK=8, 256 threads, 8x8 per thread.
// ---------------------------------------------------------------------------
__global__ void gemm_xproj(const int* __restrict__ in1, const int* __restrict__ in2,
                           const float* __restrict__ emb, const float* __restrict__ Wx) {
    __shared__ float As[8][128];
    __shared__ float Bs[8][128];
    __shared__ int   toks[128];

    const int tid  = threadIdx.x;
    const int row0 = blockIdx.y * 128;   // 480 row tiles; 1024 % 128 == 0 -> same t per tile
    const int col0 = blockIdx.x * 128;   // 16 col tiles

    if (tid < 128) {
        int r  = row0 + tid;
        int t  = r >> 10;          // / 1024
        int b2 = r & 1023;
        toks[tid] = (b2 < NB) ? in1[b2 * NT + t] : in2[(b2 - NB) * NT + t];
    }
    __syncthreads();

    float acc[8][8];
    #pragma unroll
    for (int i = 0; i < 8; i++)
        #pragma unroll
        for (int j = 0; j < 8; j++) acc[i][j] = 0.0f;

    const int tr = (tid >> 4) << 3;
    const int tc = (tid & 15) << 3;

    for (int k0 = 0; k0 < NE; k0 += 8) {
        #pragma unroll
        for (int i = 0; i < 4; i++) {
            int p  = tid * 4 + i;
            int ar = p >> 3;
            int ak = p & 7;
            float v = 0.0f;
            if (k0 + ak < NE) v = emb[(long)toks[ar] * NE + k0 + ak];
            As[ak][ar] = v;
        }
        #pragma unroll
        for (int i = 0; i < 4; i++) {
            int p  = tid * 4 + i;
            int bk = p >> 7;
            int bc = p & 127;
            float v = 0.0f;
            if (k0 + bk < NE) v = Wx[(k0 + bk) * NG + col0 + bc];
            Bs[bk][bc] = v;
        }
        __syncthreads();
        #pragma unroll
        for (int kk = 0; kk < 8; kk++) {
            float ra[8], rb[8];
            #pragma unroll
            for (int i = 0; i < 8; i++) ra[i] = As[kk][tr + i];
            #pragma unroll
            for (int j = 0; j < 8; j++) rb[j] = Bs[kk][tc + j];
            #pragma unroll
            for (int i = 0; i < 8; i++)
                #pragma unroll
                for (int j = 0; j < 8; j++) acc[i][j] += ra[i] * rb[j];
        }
        __syncthreads();
    }

    #pragma unroll
    for (int i = 0; i < 8; i++)
        #pragma unroll
        for (int j = 0; j < 8; j++)
            g_xW[(long)(row0 + tr + i) * NG + (col0 + tc + j)] = acc[i][j];
}

// ---------------------------------------------------------------------------
// Generic 128x128x8 SGEMM. M, N must be multiples of 128 (true here).
// mode 1: C = A@B + aux   (aux same layout as C, ldc)          [recurrent step]
// mode 2: C = relu(A@B + aux[col])                              [MLP layer 1]
// ---------------------------------------------------------------------------
__global__ void gemm128(const float* __restrict__ A, int lda,
                        const float* __restrict__ Bm, int ldb,
                        float* __restrict__ C, int ldc,
                        int K, int mode, const float* __restrict__ aux) {
    __shared__ float As[8][128];
    __shared__ float Bs[8][128];

    const int tid  = threadIdx.x;
    const int row0 = blockIdx.y * 128;
    const int col0 = blockIdx.x * 128;

    float acc[8][8];
    #pragma unroll
    for (int i = 0; i < 8; i++)
        #pragma unroll
        for (int j = 0; j < 8; j++) acc[i][j] = 0.0f;

    const int tr = (tid >> 4) << 3;
    const int tc = (tid & 15) << 3;

    for (int k0 = 0; k0 < K; k0 += 8) {
        #pragma unroll
        for (int i = 0; i < 4; i++) {
            int p  = tid * 4 + i;
            int ar = p >> 3;
            int ak = p & 7;
            float v = 0.0f;
            if (k0 + ak < K) v = A[(long)(row0 + ar) * lda + k0 + ak];
            As[ak][ar] = v;
        }
        #pragma unroll
        for (int i = 0; i < 4; i++) {
            int p  = tid * 4 + i;
            int bk = p >> 7;
            int bc = p & 127;
            float v = 0.0f;
            if (k0 + bk < K) v = Bm[(long)(k0 + bk) * ldb + col0 + bc];
            Bs[bk][bc] = v;
        }
        __syncthreads();
        #pragma unroll
        for (int kk = 0; kk < 8; kk++) {
            float ra[8], rb[8];
            #pragma unroll
            for (int i = 0; i < 8; i++) ra[i] = As[kk][tr + i];
            #pragma unroll
            for (int j = 0; j < 8; j++) rb[j] = Bs[kk][tc + j];
            #pragma unroll
            for (int i = 0; i < 8; i++)
                #pragma unroll
                for (int j = 0; j < 8; j++) acc[i][j] += ra[i] * rb[j];
        }
        __syncthreads();
    }

    if (mode == 1) {
        #pragma unroll
        for (int i = 0; i < 8; i++)
            #pragma unroll
            for (int j = 0; j < 8; j++) {
                long idx = (long)(row0 + tr + i) * ldc + (col0 + tc + j);
                C[idx] = acc[i][j] + aux[idx];
            }
    } else {
        #pragma unroll
        for (int i = 0; i < 8; i++)
            #pragma unroll
            for (int j = 0; j < 8; j++) {
                long idx = (long)(row0 + tr + i) * ldc + (col0 + tc + j);
                float v  = acc[i][j] + aux[col0 + tc + j];
                C[idx] = v > 0.0f ? v : 0.0f;
            }
    }
}

// ---------------------------------------------------------------------------
// LSTM cell elementwise update (gate order i, j, f, o; forget_bias = 1.0)
// ---------------------------------------------------------------------------
__global__ void lstm_cell(const float* __restrict__ bias,
                          const int* __restrict__ sl1, const int* __restrict__ sl2,
                          int t) {
    int idx = blockIdx.x * blockDim.x + threadIdx.x;
    if (idx >= NB2 * NH) return;
    int b = idx >> 9;       // / 512
    int u = idx & 511;
    const float* zr = g_z + (long)b * NG;
    float zi = zr[u]        + bias[u];
    float zj = zr[512 + u]  + bias[512 + u];
    float zf = zr[1024 + u] + bias[1024 + u];
    float zo = zr[1536 + u] + bias[1536 + u];

    float c = g_c[idx];
    float h = g_h[idx];
    float nc = c * sigmf(zf + 1.0f) + sigmf(zi) * tanhf(zj);
    float nh = tanhf(nc) * sigmf(zo);

    int sl = (b < NB) ? sl1[b] : sl2[b - NB];
    bool valid = (t < sl);
    g_c[idx] = valid ? nc : c;
    g_h[idx] = valid ? nh : h;
}

// ---------------------------------------------------------------------------
// Build h_combined [512, 2053] = [h1(513), h2(513), sub(513), dist(1), mul(513)]
// ---------------------------------------------------------------------------
__global__ void combine(const int* __restrict__ sl1, const int* __restrict__ sl2) {
    int b = blockIdx.x;                 // 512 blocks, 256 threads
    __shared__ float red[256];
    float len1 = (float)sl1[b] / (float)NT;
    float len2 = (float)sl2[b] / (float)NT;
    float lsum = 0.0f;
    float* hc = g_hc + (long)b * NHC;
    for (int k = threadIdx.x; k < NH + 1; k += 256) {
        float a = (k < NH) ? g_h[(long)b * NH + k]        : len1;
        float d = (k < NH) ? g_h[(long)(NB + b) * NH + k] : len2;
        float s = a - d;
        hc[k]          = a;
        hc[513 + k]    = d;
        hc[1026 + k]   = s;
        hc[1540 + k]   = a * d;
        lsum += s * s;
    }
    red[threadIdx.x] = lsum;
    __syncthreads();
    for (int s = 128; s > 0; s >>= 1) {
        if (threadIdx.x < s) red[threadIdx.x] += red[threadIdx.x + s];
        __syncthreads();
    }
    if (threadIdx.x == 0) hc[1539] = red[0];
}

// ---------------------------------------------------------------------------
// preds[512,2] = e1[512,256] @ W2[256,2] + b2
// ---------------------------------------------------------------------------
__global__ void final_out(const float* __restrict__ W2, const float* __restrict__ b2,
                          float* __restrict__ out) {
    int b = blockIdx.x;                 // 512 blocks, 64 threads
    __shared__ float s0[64], s1[64];
    float a0 = 0.0f, a1 = 0.0f;
    for (int k = threadIdx.x; k < NM; k += 64) {
        float e = g_e1[(long)b * NM + k];
        a0 += e * W2[k * 2 + 0];
        a1 += e * W2[k * 2 + 1];
    }
    s0[threadIdx.x] = a0;
    s1[threadIdx.x] = a1;
    __syncthreads();
    for (int s = 32; s > 0; s >>= 1) {
        if (threadIdx.x < s) { s0[threadIdx.x] += s0[threadIdx.x + s];
                               s1[threadIdx.x] += s1[threadIdx.x + s]; }
        __syncthreads();
    }
    if (threadIdx.x == 0) {
        out[b * 2 + 0] = s0[0] + b2[0];
        out[b * 2 + 1] = s1[0] + b2[1];
    }
}

// ---------------------------------------------------------------------------
extern "C" void kernel_launch(void* const* d_in, const int* in_sizes, int n_in,
                              void* d_out, int out_size) {
    const int*   in1 = (const int*)  d_in[0];
    const int*   in2 = (const int*)  d_in[1];
    const int*   sl1 = (const int*)  d_in[2];
    const int*   sl2 = (const int*)  d_in[3];
    const float* emb = (const float*)d_in[4];
    const float* lk  = (const float*)d_in[5];   // [812, 2048]
    const float* lb  = (const float*)d_in[6];
    const float* W1  = (const float*)d_in[7];   // [2053, 256]
    const float* b1  = (const float*)d_in[8];
    const float* W2  = (const float*)d_in[9];   // [256, 2]
    const float* b2  = (const float*)d_in[10];
    float* out = (float*)d_out;

    float *p_xW, *p_z, *p_h, *p_hc, *p_e1;
    cudaGetSymbolAddress((void**)&p_xW, g_xW);
    cudaGetSymbolAddress((void**)&p_z,  g_z);
    cudaGetSymbolAddress((void**)&p_h,  g_h);
    cudaGetSymbolAddress((void**)&p_hc, g_hc);
    cudaGetSymbolAddress((void**)&p_e1, g_e1);

    const float* Wh = lk + (long)NE * NG;       // recurrent rows [300..812)

    zero_state<<<(NB2 * NH + 255) / 256, 256>>>();

    // One big parallel GEMM: x@Wx for all timesteps, both sequences
    gemm_xproj<<<dim3(NG / 128, (NT * NB2) / 128), 256>>>(in1, in2, emb, lk);

    // Sequential recurrence
    for (int t = 0; t < NT; t++) {
        gemm128<<<dim3(NG / 128, NB2 / 128), 256>>>(
            p_h, NH, Wh, NG, p_z, NG, NH, 1, p_xW + (long)t * NB2 * NG);
        lstm_cell<<<(NB2 * NH + 255) / 256, 256>>>(lb, sl1, sl2, t);
    }

    combine<<<NB, 256>>>(sl1, sl2);

    // e1 = relu(hc @ W1 + b1)
    gemm128<<<dim3(NM / 128, NB / 128), 256>>>(
        p_hc, NHC, W1, NM, p_e1, NM, NHC, 2, b1);

    final_out<<<NB, 64>>>(W2, b2, out);
}

// round 3
// speedup vs baseline: 2.9520x; 2.9520x over previous
#include <cuda_runtime.h>
#include <cuda_bf16.h>
#include <math.h>
#include <stdint.h>

#define NB   512
#define NT   60
#define NE   300
#define NH   512
#define NM   256
#define NB2  1024
#define NG   2048
#define NHC  2053

// split-K concat sizes
#define KPH  512           // recurrent Kp
#define KCH  1536          // 3*KPH
#define NCH  24            // KCH/64 chunks
#define KPX  320           // xproj Kp (300 padded)
#define KCX  960           // 3*KPX
#define NCX  15

#define STAGES 3
#define STAGE_BYTES 32768  // 16KB A + 16KB B
#define DYN_SMEM (STAGES*STAGE_BYTES)

__device__ float g_xW[(size_t)NT * NB2 * NG];
__device__ float g_z [NB2 * NG];
__device__ float g_h [NB2 * NH];
__device__ float g_c [NB2 * NH];
__device__ float g_hc[NB * NHC];
__device__ float g_e1[NB * NM];
__device__ __nv_bfloat16 g_Ah[(size_t)NB2 * KCH];        // recurrent A' [hi|hi|lo]
__device__ __nv_bfloat16 g_Bh[(size_t)NG * KCH];         // Wh' [hi|lo|hi], [n][k]
__device__ __nv_bfloat16 g_Ax[(size_t)NT * NB2 * KCX];   // gathered emb' [hi|hi|lo]
__device__ __nv_bfloat16 g_Bx[(size_t)NG * KCX];         // Wx' [hi|lo|hi]

__device__ __forceinline__ float sigmf(float x) { return 1.0f / (1.0f + expf(-x)); }

#define SWZ(b) ((b) ^ (((b) >> 3) & 0x70))

__device__ __forceinline__ uint32_t smem_u32(const void* p) {
    uint32_t a;
    asm("{ .reg .u64 t; cvta.to.shared.u64 t, %1; cvt.u32.u64 %0, t; }" : "=r"(a) : "l"(p));
    return a;
}
__device__ __forceinline__ void cpasync16(uint32_t dst, const void* src) {
    asm volatile("cp.async.cg.shared.global [%0], [%1], 16;"
                 :: "r"(dst), "l"(__cvta_generic_to_global(src)));
}
#define CP_COMMIT() asm volatile("cp.async.commit_group;" ::: "memory")

__device__ __forceinline__ void ldsm_x4(uint32_t& r0, uint32_t& r1, uint32_t& r2, uint32_t& r3,
                                        uint32_t addr) {
    asm volatile("ldmatrix.sync.aligned.m8n8.x4.shared.b16 {%0,%1,%2,%3}, [%4];"
                 : "=r"(r0), "=r"(r1), "=r"(r2), "=r"(r3) : "r"(addr));
}
__device__ __forceinline__ void mma_bf16(float* c, const uint32_t* a, uint32_t b0, uint32_t b1) {
    asm volatile("mma.sync.aligned.m16n8k16.row.col.f32.bf16.bf16.f32 "
                 "{%0,%1,%2,%3}, {%4,%5,%6,%7}, {%8,%9}, {%0,%1,%2,%3};"
                 : "+f"(c[0]), "+f"(c[1]), "+f"(c[2]), "+f"(c[3])
                 : "r"(a[0]), "r"(a[1]), "r"(a[2]), "r"(a[3]), "r"(b0), "r"(b1));
}

// ---------------------------------------------------------------------------
// Zero state + A' for recurrence
// ---------------------------------------------------------------------------
__global__ void zero_init() {
    int i = blockIdx.x * 256 + threadIdx.x;
    if (i < NB2 * NH) { g_h[i] = 0.0f; g_c[i] = 0.0f; }
    if (i < NB2 * KCH) g_Ah[i] = __float2bfloat16(0.0f);
}

// ---------------------------------------------------------------------------
// Build B' = transpose + hi/lo split of W [Ksrc x 2048] -> [2048 x 3*Kp]
// segments: [0,Kp)=hi, [Kp,2Kp)=lo, [2Kp,3Kp)=hi
// ---------------------------------------------------------------------------
__global__ void build_Bcat(const float* __restrict__ W, __nv_bfloat16* __restrict__ dst,
                           int Ksrc, int Kp) {
    __shared__ float tile[32][33];
    int kb = blockIdx.x * 32, nb = blockIdx.y * 32;
    int tx = threadIdx.x, ty = threadIdx.y;     // 32 x 8
    for (int i = ty; i < 32; i += 8) {
        int k = kb + i;
        tile[i][tx] = (k < Ksrc) ? W[(size_t)k * NG + nb + tx] : 0.0f;
    }
    __syncthreads();
    for (int i = ty; i < 32; i += 8) {
        int n = nb + i, k = kb + tx;
        float v = tile[tx][i];
        __nv_bfloat16 hi = __float2bfloat16_rn(v);
        __nv_bfloat16 lo = __float2bfloat16_rn(v - __bfloat162float(hi));
        size_t base = (size_t)n * (3 * Kp);
        dst[base + k] = hi;
        dst[base + Kp + k] = lo;
        dst[base + 2 * Kp + k] = hi;
    }
}

// ---------------------------------------------------------------------------
// Build gathered A' for xproj: row r = t*1024+b2, emb[tok] split [hi|hi|lo]
// ---------------------------------------------------------------------------
__global__ void build_Ax(const int* __restrict__ in1, const int* __restrict__ in2,
                         const float* __restrict__ emb) {
    int g = blockIdx.x * 256 + threadIdx.x;
    if (g >= NT * NB2 * (KPX / 8)) return;
    int r  = g / (KPX / 8);
    int kc = (g % (KPX / 8)) * 8;
    int t  = r >> 10;
    int b2 = r & 1023;
    int tok = (b2 < NB) ? in1[b2 * NT + t] : in2[(b2 - NB) * NT + t];
    size_t base = (size_t)r * KCX;
    const float* er = emb + (size_t)tok * NE;
    #pragma unroll
    for (int j = 0; j < 8; j++) {
        int k = kc + j;
        float v = (k < NE) ? er[k] : 0.0f;
        __nv_bfloat16 hi = __float2bfloat16_rn(v);
        __nv_bfloat16 lo = __float2bfloat16_rn(v - __bfloat162float(hi));
        g_Ax[base + k] = hi;
        g_Ax[base + KPX + k] = hi;
        g_Ax[base + 2 * KPX + k] = lo;
    }
}

// ---------------------------------------------------------------------------
// bf16 mma.sync GEMM: C[M,2048] = A'[M,Kc] @ B'[2048,Kc]^T (fp32 accum)
// CTA 128x128, BK=64, 3-stage cp.async, 8 warps (2x4) of 64x32.
// ---------------------------------------------------------------------------
__global__ void __launch_bounds__(256)
gemm_mma(const __nv_bfloat16* __restrict__ A, const __nv_bfloat16* __restrict__ B,
         float* __restrict__ C, int ldab, int NC) {
    extern __shared__ char dsm[];
    const int tid  = threadIdx.x;
    const int wid  = tid >> 5;
    const int lane = tid & 31;
    const int row0 = blockIdx.y * 128;
    const int col0 = blockIdx.x * 128;
    const int wm0  = (wid & 1) * 64;   // warp m offset in tile
    const int wn0  = (wid >> 1) * 32;  // warp n offset in tile
    const uint32_t sm = smem_u32(dsm);

    const __nv_bfloat16* aRow = A + (size_t)row0 * ldab;
    const __nv_bfloat16* bRow = B + (size_t)col0 * ldab;

    auto load_chunk = [&](int c, int st) {
        uint32_t aB = sm + st * STAGE_BYTES;
        uint32_t bB = aB + 16384;
        const __nv_bfloat16* aS = aRow + c * 64;
        const __nv_bfloat16* bS = bRow + c * 64;
        #pragma unroll
        for (int i = 0; i < 4; i++) {
            int idx = i * 256 + tid;
            int r = idx >> 3, s = idx & 7;
            cpasync16(aB + SWZ(r * 128 + s * 16), aS + (size_t)r * ldab + s * 8);
        }
        #pragma unroll
        for (int i = 0; i < 4; i++) {
            int idx = i * 256 + tid;
            int n = idx >> 3, s = idx & 7;
            cpasync16(bB + SWZ(n * 128 + s * 16), bS + (size_t)n * ldab + s * 8);
        }
    };

    float acc[4][4][4];
    #pragma unroll
    for (int i = 0; i < 4; i++)
        #pragma unroll
        for (int j = 0; j < 4; j++)
            #pragma unroll
            for (int k = 0; k < 4; k++) acc[i][j][k] = 0.0f;

    for (int s = 0; s < STAGES && s < NC; s++) { load_chunk(s, s); CP_COMMIT(); }

    // precomputed ldmatrix lane address components
    const int a_row = wm0 + (lane & 15);           // + mf*16
    const int a_colb = 16 * (lane >> 4);           // + kk*32
    const int b_row = wn0 + lane;                  // n index
    for (int c = 0; c < NC; c++) {
        int st = c % STAGES;
        int rem = NC - 1 - c;
        if (rem >= 2)      asm volatile("cp.async.wait_group 2;" ::: "memory");
        else if (rem == 1) asm volatile("cp.async.wait_group 1;" ::: "memory");
        else               asm volatile("cp.async.wait_group 0;" ::: "memory");
        __syncthreads();

        uint32_t aB = sm + st * STAGE_BYTES;
        uint32_t bB = aB + 16384;
        #pragma unroll
        for (int kk = 0; kk < 4; kk++) {
            uint32_t a[4][4];
            #pragma unroll
            for (int mf = 0; mf < 4; mf++) {
                uint32_t addr = aB + SWZ((a_row + mf * 16) * 128 + kk * 32 + a_colb);
                ldsm_x4(a[mf][0], a[mf][1], a[mf][2], a[mf][3], addr);
            }
            uint32_t blo[4], bhi[4];
            {
                uint32_t addr0 = bB + SWZ(b_row * 128 + kk * 32);
                ldsm_x4(blo[0], blo[1], blo[2], blo[3], addr0);
                uint32_t addr1 = bB + SWZ(b_row * 128 + kk * 32 + 16);
                ldsm_x4(bhi[0], bhi[1], bhi[2], bhi[3], addr1);
            }
            #pragma unroll
            for (int mf = 0; mf < 4; mf++)
                #pragma unroll
                for (int nf = 0; nf < 4; nf++)
                    mma_bf16(acc[mf][nf], a[mf], blo[nf], bhi[nf]);
        }
        __syncthreads();
        if (c + STAGES < NC) { load_chunk(c + STAGES, st); CP_COMMIT(); }
    }

    // epilogue
    const int gid = lane >> 2, tig = lane & 3;
    #pragma unroll
    for (int mf = 0; mf < 4; mf++) {
        #pragma unroll
        for (int nf = 0; nf < 4; nf++) {
            size_t row = (size_t)row0 + wm0 + mf * 16 + gid;
            size_t col = (size_t)col0 + wn0 + nf * 8 + tig * 2;
            float2 v0 = make_float2(acc[mf][nf][0], acc[mf][nf][1]);
            float2 v1 = make_float2(acc[mf][nf][2], acc[mf][nf][3]);
            *reinterpret_cast<float2*>(C + row * NG + col)       = v0;
            *reinterpret_cast<float2*>(C + (row + 8) * NG + col) = v1;
        }
    }
}

// ---------------------------------------------------------------------------
// LSTM cell: xW(+z)(+bias) -> gates -> masked update; writes h,c and next A'
// ---------------------------------------------------------------------------
__global__ void lstm_cell(const float* __restrict__ bias, const int* __restrict__ sl1,
                          const int* __restrict__ sl2, int t, int use_z) {
    int idx = blockIdx.x * 256 + threadIdx.x;
    if (idx >= NB2 * NH / 4) return;
    int b = idx >> 7;
    int u = (idx & 127) << 2;

    const float* xw = g_xW + ((size_t)t * NB2 + b) * NG + u;
    float4 gi = *(const float4*)(xw);
    float4 gj = *(const float4*)(xw + 512);
    float4 gf = *(const float4*)(xw + 1024);
    float4 go = *(const float4*)(xw + 1536);
    if (use_z) {
        const float* zr = g_z + (size_t)b * NG + u;
        float4 a;
        a = *(const float4*)(zr);        gi.x += a.x; gi.y += a.y; gi.z += a.z; gi.w += a.w;
        a = *(const float4*)(zr + 512);  gj.x += a.x; gj.y += a.y; gj.z += a.z; gj.w += a.w;
        a = *(const float4*)(zr + 1024); gf.x += a.x; gf.y += a.y; gf.z += a.z; gf.w += a.w;
        a = *(const float4*)(zr + 1536); go.x += a.x; go.y += a.y; go.z += a.z; go.w += a.w;
    }
    {
        float4 a;
        a = *(const float4*)(bias + u);        gi.x += a.x; gi.y += a.y; gi.z += a.z; gi.w += a.w;
        a = *(const float4*)(bias + 512 + u);  gj.x += a.x; gj.y += a.y; gj.z += a.z; gj.w += a.w;
        a = *(const float4*)(bias + 1024 + u); gf.x += a.x; gf.y += a.y; gf.z += a.z; gf.w += a.w;
        a = *(const float4*)(bias + 1536 + u); go.x += a.x; go.y += a.y; go.z += a.z; go.w += a.w;
    }
    int sl = (b < NB) ? sl1[b] : sl2[b - NB];
    if (t >= sl) return;  // state & A' unchanged

    float4 c4 = *(const float4*)(g_c + (size_t)b * NH + u);
    float nc[4], nh[4];
    float zi[4] = {gi.x, gi.y, gi.z, gi.w};
    float zj[4] = {gj.x, gj.y, gj.z, gj.w};
    float zf[4] = {gf.x, gf.y, gf.z, gf.w};
    float zo[4] = {go.x, go.y, go.z, go.w};
    float cc[4] = {c4.x, c4.y, c4.z, c4.w};
    #pragma unroll
    for (int k = 0; k < 4; k++) {
        nc[k] = cc[k] * sigmf(zf[k] + 1.0f) + sigmf(zi[k]) * tanhf(zj[k]);
        nh[k] = tanhf(nc[k]) * sigmf(zo[k]);
    }
    *(float4*)(g_c + (size_t)b * NH + u) = make_float4(nc[0], nc[1], nc[2], nc[3]);
    *(float4*)(g_h + (size_t)b * NH + u) = make_float4(nh[0], nh[1], nh[2], nh[3]);

    __nv_bfloat16 hi[4], lo[4];
    #pragma unroll
    for (int k = 0; k < 4; k++) {
        hi[k] = __float2bfloat16_rn(nh[k]);
        lo[k] = __float2bfloat16_rn(nh[k] - __bfloat162float(hi[k]));
    }
    __nv_bfloat16* ar = g_Ah + (size_t)b * KCH;
    __nv_bfloat162 h01, h23, l01, l23;
    h01.x = hi[0]; h01.y = hi[1]; h23.x = hi[2]; h23.y = hi[3];
    l01.x = lo[0]; l01.y = lo[1]; l23.x = lo[2]; l23.y = lo[3];
    *(__nv_bfloat162*)(ar + u)            = h01;
    *(__nv_bfloat162*)(ar + u + 2)        = h23;
    *(__nv_bfloat162*)(ar + KPH + u)      = h01;
    *(__nv_bfloat162*)(ar + KPH + u + 2)  = h23;
    *(__nv_bfloat162*)(ar + 2 * KPH + u)     = l01;
    *(__nv_bfloat162*)(ar + 2 * KPH + u + 2) = l23;
}

// ---------------------------------------------------------------------------
// SIMT 128x128 SGEMM for MLP layer 1: C = relu(A@B + aux[col])
// ---------------------------------------------------------------------------
__global__ void gemm128(const float* __restrict__ A, int lda,
                        const float* __restrict__ Bm, int ldb,
                        float* __restrict__ C, int ldc,
                        int K, const float* __restrict__ aux) {
    __shared__ float As[8][128];
    __shared__ float Bs[8][128];
    const int tid  = threadIdx.x;
    const int row0 = blockIdx.y * 128;
    const int col0 = blockIdx.x * 128;
    float acc[8][8];
    #pragma unroll
    for (int i = 0; i < 8; i++)
        #pragma unroll
        for (int j = 0; j < 8; j++) acc[i][j] = 0.0f;
    const int tr = (tid >> 4) << 3;
    const int tc = (tid & 15) << 3;
    for (int k0 = 0; k0 < K; k0 += 8) {
        #pragma unroll
        for (int i = 0; i < 4; i++) {
            int p = tid * 4 + i, ar = p >> 3, ak = p & 7;
            As[ak][ar] = (k0 + ak < K) ? A[(size_t)(row0 + ar) * lda + k0 + ak] : 0.0f;
        }
        #pragma unroll
        for (int i = 0; i < 4; i++) {
            int p = tid * 4 + i, bk = p >> 7, bc = p & 127;
            Bs[bk][bc] = (k0 + bk < K) ? Bm[(size_t)(k0 + bk) * ldb + col0 + bc] : 0.0f;
        }
        __syncthreads();
        #pragma unroll
        for (int kk = 0; kk < 8; kk++) {
            float ra[8], rb[8];
            #pragma unroll
            for (int i = 0; i < 8; i++) ra[i] = As[kk][tr + i];
            #pragma unroll
            for (int j = 0; j < 8; j++) rb[j] = Bs[kk][tc + j];
            #pragma unroll
            for (int i = 0; i < 8; i++)
                #pragma unroll
                for (int j = 0; j < 8; j++) acc[i][j] += ra[i] * rb[j];
        }
        __syncthreads();
    }
    #pragma unroll
    for (int i = 0; i < 8; i++)
        #pragma unroll
        for (int j = 0; j < 8; j++) {
            size_t idx = (size_t)(row0 + tr + i) * ldc + (col0 + tc + j);
            float v = acc[i][j] + aux[col0 + tc + j];
            C[idx] = v > 0.0f ? v : 0.0f;
        }
}

// ---------------------------------------------------------------------------
__global__ void combine(const int* __restrict__ sl1, const int* __restrict__ sl2) {
    int b = blockIdx.x;
    __shared__ float red[256];
    float len1 = (float)sl1[b] / (float)NT;
    float len2 = (float)sl2[b] / (float)NT;
    float lsum = 0.0f;
    float* hc = g_hc + (size_t)b * NHC;
    for (int k = threadIdx.x; k < NH + 1; k += 256) {
        float a = (k < NH) ? g_h[(size_t)b * NH + k]        : len1;
        float d = (k < NH) ? g_h[(size_t)(NB + b) * NH + k] : len2;
        float s = a - d;
        hc[k]        = a;
        hc[513 + k]  = d;
        hc[1026 + k] = s;
        hc[1540 + k] = a * d;
        lsum += s * s;
    }
    red[threadIdx.x] = lsum;
    __syncthreads();
    for (int s = 128; s > 0; s >>= 1) {
        if (threadIdx.x < s) red[threadIdx.x] += red[threadIdx.x + s];
        __syncthreads();
    }
    if (threadIdx.x == 0) hc[1539] = red[0];
}

__global__ void final_out(const float* __restrict__ W2, const float* __restrict__ b2,
                          float* __restrict__ out) {
    int b = blockIdx.x;
    __shared__ float s0[64], s1[64];
    float a0 = 0.0f, a1 = 0.0f;
    for (int k = threadIdx.x; k < NM; k += 64) {
        float e = g_e1[(size_t)b * NM + k];
        a0 += e * W2[k * 2 + 0];
        a1 += e * W2[k * 2 + 1];
    }
    s0[threadIdx.x] = a0;
    s1[threadIdx.x] = a1;
    __syncthreads();
    for (int s = 32; s > 0; s >>= 1) {
        if (threadIdx.x < s) { s0[threadIdx.x] += s0[threadIdx.x + s];
                               s1[threadIdx.x] += s1[threadIdx.x + s]; }
        __syncthreads();
    }
    if (threadIdx.x == 0) {
        out[b * 2 + 0] = s0[0] + b2[0];
        out[b * 2 + 1] = s1[0] + b2[1];
    }
}

// ---------------------------------------------------------------------------
extern "C" void kernel_launch(void* const* d_in, const int* in_sizes, int n_in,
                              void* d_out, int out_size) {
    const int*   in1 = (const int*)  d_in[0];
    const int*   in2 = (const int*)  d_in[1];
    const int*   sl1 = (const int*)  d_in[2];
    const int*   sl2 = (const int*)  d_in[3];
    const float* emb = (const float*)d_in[4];
    const float* lk  = (const float*)d_in[5];
    const float* lb  = (const float*)d_in[6];
    const float* W1  = (const float*)d_in[7];
    const float* b1  = (const float*)d_in[8];
    const float* W2  = (const float*)d_in[9];
    const float* b2  = (const float*)d_in[10];
    float* out = (float*)d_out;

    float *p_xW, *p_z, *p_hc, *p_e1;
    __nv_bfloat16 *p_Ah, *p_Bh, *p_Ax, *p_Bx;
    cudaGetSymbolAddress((void**)&p_xW, g_xW);
    cudaGetSymbolAddress((void**)&p_z,  g_z);
    cudaGetSymbolAddress((void**)&p_hc, g_hc);
    cudaGetSymbolAddress((void**)&p_e1, g_e1);
    cudaGetSymbolAddress((void**)&p_Ah, g_Ah);
    cudaGetSymbolAddress((void**)&p_Bh, g_Bh);
    cudaGetSymbolAddress((void**)&p_Ax, g_Ax);
    cudaGetSymbolAddress((void**)&p_Bx, g_Bx);

    cudaFuncSetAttribute(gemm_mma, cudaFuncAttributeMaxDynamicSharedMemorySize, DYN_SMEM);

    const float* Wh = lk + (size_t)NE * NG;

    zero_init<<<(NB2 * KCH + 255) / 256, 256>>>();
    build_Bcat<<<dim3(KPH / 32, NG / 32), dim3(32, 8)>>>(Wh, p_Bh, NH, KPH);
    build_Bcat<<<dim3(KPX / 32, NG / 32), dim3(32, 8)>>>(lk, p_Bx, NE, KPX);
    build_Ax<<<(NT * NB2 * (KPX / 8) + 255) / 256, 256>>>(in1, in2, emb);

    // xproj: xW[all t] = emb' @ Wx'
    gemm_mma<<<dim3(NG / 128, NT * NB2 / 128), 256, DYN_SMEM>>>(p_Ax, p_Bx, p_xW, KCX, NCX);

    for (int t = 0; t < NT; t++) {
        if (t > 0)
            gemm_mma<<<dim3(NG / 128, NB2 / 128), 256, DYN_SMEM>>>(p_Ah, p_Bh, p_z, KCH, NCH);
        lstm_cell<<<(NB2 * NH / 4 + 255) / 256, 256>>>(lb, sl1, sl2, t, t > 0);
    }

    combine<<<NB, 256>>>(sl1, sl2);
    gemm128<<<dim3(NM / 128, NB / 128), 256>>>(p_hc, NHC, W1, NM, p_e1, NM, NHC, b1);
    final_out<<<NB, 64>>>(W2, b2, out);
}